// round 11
// baseline (speedup 1.0000x reference)
#include <cuda_runtime.h>
#include <cuda_fp16.h>
#include <cstdint>

#define BATCH 512
#define NNEG  2048
#define EDIM  256
#define KDIM  512           // pure fp16: K = 2*E
#define KC    128           // fp16 K per outer chunk (2 x 64 sub-slabs)
#define NCH   (KDIM / KC)   // 4 outer chunks
#define STG   3

// Scratch
__device__ __align__(16) __half g_Ah[BATCH * KDIM];
__device__ __align__(16) __half g_Bh[NNEG  * KDIM];
__device__ float g_c[BATCH];
__device__ unsigned long long g_bar;   // monotonic grid-barrier counter

#define BM 64
#define BN 64
#define STAGE_BYTES 32768                 // A 16KB + B 16KB
#define SM_TOTAL    (STG * STAGE_BYTES)   // 96KB

__device__ __forceinline__ uint32_t s2u(const void* p) {
    uint32_t a;
    asm("{ .reg .u64 t; cvta.to.shared.u64 t, %1; cvt.u32.u64 %0, t; }" : "=r"(a) : "l"(p));
    return a;
}
__device__ __forceinline__ uint32_t sw128(uint32_t off) {
    return off ^ ((off >> 3) & 0x70);
}
__device__ __forceinline__ void cpasync16(uint32_t dst, const void* src) {
    asm volatile("cp.async.cg.shared.global [%0], [%1], 16;" :: "r"(dst), "l"(src));
}
__device__ __forceinline__ float wredsum(float v) {
    #pragma unroll
    for (int o = 16; o > 0; o >>= 1) v += __shfl_xor_sync(0xffffffffu, v, o);
    return v;
}
__device__ __forceinline__ uint4 pack8(const float* v) {
    union { uint4 u; __half2 h[4]; } r;
    r.h[0] = __floats2half2_rn(v[0], v[1]);
    r.h[1] = __floats2half2_rn(v[2], v[3]);
    r.h[2] = __floats2half2_rn(v[4], v[5]);
    r.h[3] = __floats2half2_rn(v[6], v[7]);
    return r.u;
}

// ---------------------------------------------------------------------------
// Fused kernel: pipelined prep -> grid barrier -> HMMA GEMM.
// 64x64 tile, 256 CTAs, 4 warps, fp16 K=512 in 4 chunks of 128 (3-stage).
// ---------------------------------------------------------------------------
__global__ void __launch_bounds__(128, 2)
fused_kernel(float* __restrict__ out,
             const float* __restrict__ head,
             const float* __restrict__ tail,
             const float* __restrict__ rel,
             const int* __restrict__ rid) {
    extern __shared__ __align__(128) char smem[];

    int tid = threadIdx.x;
    int lane = tid & 31;
    int wid = tid >> 5;                        // 0..3
    int flat = blockIdx.y * 32 + blockIdx.x;   // 0..255
    int e0 = lane * 8;

    // ======== Phase 1: pipelined prep (R10, known good) ========
    {
        bool hasA = (wid < 2);
        int b  = flat * 2 + wid;
        int j0 = flat * 8 + wid;
        int j1 = j0 + 4;

        float hv[8];
        int r = 0;
        if (hasA) {
            *reinterpret_cast<float4*>(hv)     = *reinterpret_cast<const float4*>(&head[b * EDIM + e0]);
            *reinterpret_cast<float4*>(hv + 4) = *reinterpret_cast<const float4*>(&head[b * EDIM + e0 + 4]);
            r = __ldg(&rid[b]);
        }
        float tv0[8], tv1[8];
        *reinterpret_cast<float4*>(tv0)     = *reinterpret_cast<const float4*>(&tail[j0 * EDIM + e0]);
        *reinterpret_cast<float4*>(tv0 + 4) = *reinterpret_cast<const float4*>(&tail[j0 * EDIM + e0 + 4]);
        *reinterpret_cast<float4*>(tv1)     = *reinterpret_cast<const float4*>(&tail[j1 * EDIM + e0]);
        *reinterpret_cast<float4*>(tv1 + 4) = *reinterpret_cast<const float4*>(&tail[j1 * EDIM + e0 + 4]);

        float rh[8], rt[8];
        if (hasA) {
            const float* rrow = rel + (size_t)r * KDIM;
            *reinterpret_cast<float4*>(rh)     = *reinterpret_cast<const float4*>(&rrow[e0]);
            *reinterpret_cast<float4*>(rh + 4) = *reinterpret_cast<const float4*>(&rrow[e0 + 4]);
            *reinterpret_cast<float4*>(rt)     = *reinterpret_cast<const float4*>(&rrow[EDIM + e0]);
            *reinterpret_cast<float4*>(rt + 4) = *reinterpret_cast<const float4*>(&rrow[EDIM + e0 + 4]);
        }
        {
            float s = 0.f;
            #pragma unroll
            for (int i = 0; i < 8; i++) s += tv0[i] * tv0[i];
            s = wredsum(s);
            float inv = 1.f / fmaxf(sqrtf(s), 1e-12f);
            float w1[8], w2[8];
            #pragma unroll
            for (int i = 0; i < 8; i++) {
                float tn = tv0[i] * inv;
                w1[i] = tn * tn;
                w2[i] = tn;
            }
            size_t rb = (size_t)j0 * KDIM;
            *reinterpret_cast<uint4*>(&g_Bh[rb + e0])        = pack8(w1);
            *reinterpret_cast<uint4*>(&g_Bh[rb + EDIM + e0]) = pack8(w2);
        }
        {
            float s = 0.f;
            #pragma unroll
            for (int i = 0; i < 8; i++) s += tv1[i] * tv1[i];
            s = wredsum(s);
            float inv = 1.f / fmaxf(sqrtf(s), 1e-12f);
            float w1[8], w2[8];
            #pragma unroll
            for (int i = 0; i < 8; i++) {
                float tn = tv1[i] * inv;
                w1[i] = tn * tn;
                w2[i] = tn;
            }
            size_t rb = (size_t)j1 * KDIM;
            *reinterpret_cast<uint4*>(&g_Bh[rb + e0])        = pack8(w1);
            *reinterpret_cast<uint4*>(&g_Bh[rb + EDIM + e0]) = pack8(w2);
        }
        if (hasA) {
            float s = 0.f;
            #pragma unroll
            for (int i = 0; i < 8; i++) s += hv[i] * hv[i];
            s = wredsum(s);
            float inv = 1.f / fmaxf(sqrtf(s), 1e-12f);
            float v1[8], v2[8], cs = 0.f;
            #pragma unroll
            for (int i = 0; i < 8; i++) {
                float hh = hv[i] * inv * rh[i];
                v1[i] = rt[i] * rt[i];
                v2[i] = -2.f * rt[i] * hh;
                cs += hh * hh;
            }
            size_t ra = (size_t)b * KDIM;
            *reinterpret_cast<uint4*>(&g_Ah[ra + e0])        = pack8(v1);
            *reinterpret_cast<uint4*>(&g_Ah[ra + EDIM + e0]) = pack8(v2);
            cs = wredsum(cs);
            if (lane == 0) g_c[b] = cs;
        }
    }
    __threadfence();

    // ======== Phase 2: grid barrier (monotonic generation; replay-safe) ========
    __syncthreads();
    if (tid == 0) {
        unsigned long long ticket = atomicAdd(&g_bar, 1ULL);
        unsigned long long target = ((ticket >> 8) + 1) << 8;
        unsigned long long cur;
        do {
            asm volatile("ld.acquire.gpu.global.u64 %0, [%1];"
                         : "=l"(cur) : "l"(&g_bar));
            if (cur >= target) break;
            __nanosleep(64);
        } while (true);
    }
    __syncthreads();

    // ======== Phase 3: GEMM ========
    int wm = wid & 1;
    int wn = wid >> 1;
    int bn0 = blockIdx.x * BN;
    int bm0 = blockIdx.y * BM;
    int groupID = lane >> 2;
    int tig = lane & 3;

    // prefetch per-row constants (hide LDG latency behind the mainloop)
    int er0 = bm0 + wm * 32 + groupID;
    float cpre[2][2];
    cpre[0][0] = g_c[er0];
    cpre[0][1] = g_c[er0 + 8];
    cpre[1][0] = g_c[er0 + 16];
    cpre[1][1] = g_c[er0 + 24];

    float acc[2][4][4];
    #pragma unroll
    for (int mi = 0; mi < 2; mi++)
        #pragma unroll
        for (int ni = 0; ni < 4; ni++)
            #pragma unroll
            for (int q = 0; q < 4; q++) acc[mi][ni][q] = 0.f;

    uint32_t sbase = s2u(smem);

    int aRow = (lane & 7) + ((lane >> 3) & 1) * 8;
    int aKh  = (lane >> 4) * 8;
    int bRowOff = ((lane >> 4) & 1) * 8 + (lane & 7);
    int bKh     = ((lane >> 3) & 1) * 8;

    // issue outer chunk ic (128 k) into stage ic%STG: two 64-k sub-slabs.
    auto issue = [&](int ic) {
        if (ic < NCH) {
            uint32_t sD = sbase + (ic % STG) * STAGE_BYTES;
            int k0 = ic * KC;
            #pragma unroll
            for (int h = 0; h < 2; h++) {
                uint32_t aD = sD + h * 8192;
                uint32_t bD = sD + 16384 + h * 8192;
                int kh = k0 + h * 64;
                #pragma unroll
                for (int i = 0; i < 4; i++) {
                    int idx = i * 128 + tid;
                    int r = idx >> 3, c = idx & 7;
                    cpasync16(aD + sw128(r * 128 + c * 16),
                              &g_Ah[(size_t)(bm0 + r) * KDIM + kh + c * 8]);
                    cpasync16(bD + sw128(r * 128 + c * 16),
                              &g_Bh[(size_t)(bn0 + r) * KDIM + kh + c * 8]);
                }
            }
        }
        asm volatile("cp.async.commit_group;" ::: "memory");
    };

    issue(0);
    issue(1);

    #pragma unroll
    for (int it = 0; it < NCH; it++) {
        asm volatile("cp.async.wait_group 1;" ::: "memory");
        __syncthreads();
        issue(it + 2);

        uint32_t sB = sbase + (it % STG) * STAGE_BYTES;

        #pragma unroll
        for (int kk = 0; kk < 8; kk++) {       // 8 k-steps of 16
            uint32_t aBase = sB + (kk >> 2) * 8192;
            uint32_t bBase = sB + 16384 + (kk >> 2) * 8192;
            int kq = kk & 3;

            uint32_t af[2][4];
            #pragma unroll
            for (int mi = 0; mi < 2; mi++) {
                int row = wm * 32 + mi * 16 + aRow;
                int kcol = kq * 16 + aKh;
                uint32_t addr = aBase + sw128((uint32_t)(row * 128 + kcol * 2));
                asm volatile(
                    "ldmatrix.sync.aligned.m8n8.x4.shared.b16 {%0,%1,%2,%3}, [%4];"
                    : "=r"(af[mi][0]), "=r"(af[mi][1]), "=r"(af[mi][2]), "=r"(af[mi][3])
                    : "r"(addr));
            }
            uint32_t bf[4][2];
            #pragma unroll
            for (int p = 0; p < 2; p++) {
                int n = wn * 32 + p * 16 + bRowOff;
                int kcol = kq * 16 + bKh;
                uint32_t addr = bBase + sw128((uint32_t)(n * 128 + kcol * 2));
                asm volatile(
                    "ldmatrix.sync.aligned.m8n8.x4.shared.b16 {%0,%1,%2,%3}, [%4];"
                    : "=r"(bf[p * 2][0]), "=r"(bf[p * 2][1]),
                      "=r"(bf[p * 2 + 1][0]), "=r"(bf[p * 2 + 1][1])
                    : "r"(addr));
            }
            #pragma unroll
            for (int mi = 0; mi < 2; mi++)
                #pragma unroll
                for (int ni = 0; ni < 4; ni++) {
                    asm volatile(
                        "mma.sync.aligned.m16n8k16.row.col.f32.f16.f16.f32 "
                        "{%0,%1,%2,%3}, {%4,%5,%6,%7}, {%8,%9}, {%0,%1,%2,%3};"
                        : "+f"(acc[mi][ni][0]), "+f"(acc[mi][ni][1]),
                          "+f"(acc[mi][ni][2]), "+f"(acc[mi][ni][3])
                        : "r"(af[mi][0]), "r"(af[mi][1]), "r"(af[mi][2]), "r"(af[mi][3]),
                          "r"(bf[ni][0]), "r"(bf[ni][1]));
                }
        }
    }

    #pragma unroll
    for (int mi = 0; mi < 2; mi++) {
        int r0 = bm0 + wm * 32 + mi * 16 + groupID;
        int r1 = r0 + 8;
        float c0 = cpre[mi][0];
        float c1 = cpre[mi][1];
        #pragma unroll
        for (int ni = 0; ni < 4; ni++) {
            int col = bn0 + wn * 32 + ni * 8 + tig * 2;
            float2 v0, v1;
            v0.x = -sqrtf(fmaxf(acc[mi][ni][0] + c0, 0.f));
            v0.y = -sqrtf(fmaxf(acc[mi][ni][1] + c0, 0.f));
            v1.x = -sqrtf(fmaxf(acc[mi][ni][2] + c1, 0.f));
            v1.y = -sqrtf(fmaxf(acc[mi][ni][3] + c1, 0.f));
            *reinterpret_cast<float2*>(out + (size_t)r0 * NNEG + col) = v0;
            *reinterpret_cast<float2*>(out + (size_t)r1 * NNEG + col) = v1;
        }
    }
}

// ---------------------------------------------------------------------------
extern "C" void kernel_launch(void* const* d_in, const int* in_sizes, int n_in,
                              void* d_out, int out_size) {
    const float* head = (const float*)d_in[0];       // (512, 256)
    const float* tail = (const float*)d_in[1];       // (1, 2048, 256)
    const float* rel  = (const float*)d_in[2];       // (1000, 512)
    const int*   rid  = (const int*)d_in[3];         // (512,) int32
    float* out = (float*)d_out;                      // (512, 2048)

    cudaFuncSetAttribute(fused_kernel,
                         cudaFuncAttributeMaxDynamicSharedMemorySize, SM_TOTAL);
    dim3 grid(NNEG / BN, BATCH / BM);                // 32 x 8 = 256 CTAs
    fused_kernel<<<grid, 128, SM_TOTAL>>>(out, head, tail, rel, rid);
}

// round 12
// speedup vs baseline: 1.0201x; 1.0201x over previous
#include <cuda_runtime.h>
#include <cuda_fp16.h>
#include <cstdint>

#define BATCH 512
#define NNEG  2048
#define EDIM  256
#define KDIM  512           // pure fp16: K = 2*E
#define KC    128           // fp16 K per outer chunk (2 x 64 sub-slabs)
#define NCH   (KDIM / KC)   // 4 outer chunks
#define STG   3

// Scratch
__device__ __align__(16) __half g_Ah[BATCH * KDIM];
__device__ __align__(16) __half g_Bh[NNEG  * KDIM];
__device__ float g_c[BATCH];
__device__ unsigned long long g_bar;   // monotonic grid-barrier counter

#define BM 64
#define BN 64
#define STAGE_BYTES 32768                 // A 16KB + B 16KB
#define SM_TOTAL    (STG * STAGE_BYTES)   // 96KB

__device__ __forceinline__ uint32_t s2u(const void* p) {
    uint32_t a;
    asm("{ .reg .u64 t; cvta.to.shared.u64 t, %1; cvt.u32.u64 %0, t; }" : "=r"(a) : "l"(p));
    return a;
}
__device__ __forceinline__ uint32_t sw128(uint32_t off) {
    return off ^ ((off >> 3) & 0x70);
}
__device__ __forceinline__ void cpasync16(uint32_t dst, const void* src) {
    asm volatile("cp.async.cg.shared.global [%0], [%1], 16;" :: "r"(dst), "l"(src));
}
__device__ __forceinline__ float wredsum(float v) {
    #pragma unroll
    for (int o = 16; o > 0; o >>= 1) v += __shfl_xor_sync(0xffffffffu, v, o);
    return v;
}
__device__ __forceinline__ uint4 pack8(const float* v) {
    union { uint4 u; __half2 h[4]; } r;
    r.h[0] = __floats2half2_rn(v[0], v[1]);
    r.h[1] = __floats2half2_rn(v[2], v[3]);
    r.h[2] = __floats2half2_rn(v[4], v[5]);
    r.h[3] = __floats2half2_rn(v[6], v[7]);
    return r.u;
}

// ---------------------------------------------------------------------------
// Fused kernel: pipelined prep -> grid barrier -> HMMA GEMM with
// register-level fragment double-buffering.
// ---------------------------------------------------------------------------
__global__ void __launch_bounds__(128, 2)
fused_kernel(float* __restrict__ out,
             const float* __restrict__ head,
             const float* __restrict__ tail,
             const float* __restrict__ rel,
             const int* __restrict__ rid) {
    extern __shared__ __align__(128) char smem[];

    int tid = threadIdx.x;
    int lane = tid & 31;
    int wid = tid >> 5;                        // 0..3
    int flat = blockIdx.y * 32 + blockIdx.x;   // 0..255
    int e0 = lane * 8;

    // ======== Phase 1: pipelined prep (R10/R11, known good) ========
    {
        bool hasA = (wid < 2);
        int b  = flat * 2 + wid;
        int j0 = flat * 8 + wid;
        int j1 = j0 + 4;

        float hv[8];
        int r = 0;
        if (hasA) {
            *reinterpret_cast<float4*>(hv)     = *reinterpret_cast<const float4*>(&head[b * EDIM + e0]);
            *reinterpret_cast<float4*>(hv + 4) = *reinterpret_cast<const float4*>(&head[b * EDIM + e0 + 4]);
            r = __ldg(&rid[b]);
        }
        float tv0[8], tv1[8];
        *reinterpret_cast<float4*>(tv0)     = *reinterpret_cast<const float4*>(&tail[j0 * EDIM + e0]);
        *reinterpret_cast<float4*>(tv0 + 4) = *reinterpret_cast<const float4*>(&tail[j0 * EDIM + e0 + 4]);
        *reinterpret_cast<float4*>(tv1)     = *reinterpret_cast<const float4*>(&tail[j1 * EDIM + e0]);
        *reinterpret_cast<float4*>(tv1 + 4) = *reinterpret_cast<const float4*>(&tail[j1 * EDIM + e0 + 4]);

        float rh[8], rt[8];
        if (hasA) {
            const float* rrow = rel + (size_t)r * KDIM;
            *reinterpret_cast<float4*>(rh)     = *reinterpret_cast<const float4*>(&rrow[e0]);
            *reinterpret_cast<float4*>(rh + 4) = *reinterpret_cast<const float4*>(&rrow[e0 + 4]);
            *reinterpret_cast<float4*>(rt)     = *reinterpret_cast<const float4*>(&rrow[EDIM + e0]);
            *reinterpret_cast<float4*>(rt + 4) = *reinterpret_cast<const float4*>(&rrow[EDIM + e0 + 4]);
        }
        {
            float s = 0.f;
            #pragma unroll
            for (int i = 0; i < 8; i++) s += tv0[i] * tv0[i];
            s = wredsum(s);
            float inv = 1.f / fmaxf(sqrtf(s), 1e-12f);
            float w1[8], w2[8];
            #pragma unroll
            for (int i = 0; i < 8; i++) {
                float tn = tv0[i] * inv;
                w1[i] = tn * tn;
                w2[i] = tn;
            }
            size_t rb = (size_t)j0 * KDIM;
            *reinterpret_cast<uint4*>(&g_Bh[rb + e0])        = pack8(w1);
            *reinterpret_cast<uint4*>(&g_Bh[rb + EDIM + e0]) = pack8(w2);
        }
        {
            float s = 0.f;
            #pragma unroll
            for (int i = 0; i < 8; i++) s += tv1[i] * tv1[i];
            s = wredsum(s);
            float inv = 1.f / fmaxf(sqrtf(s), 1e-12f);
            float w1[8], w2[8];
            #pragma unroll
            for (int i = 0; i < 8; i++) {
                float tn = tv1[i] * inv;
                w1[i] = tn * tn;
                w2[i] = tn;
            }
            size_t rb = (size_t)j1 * KDIM;
            *reinterpret_cast<uint4*>(&g_Bh[rb + e0])        = pack8(w1);
            *reinterpret_cast<uint4*>(&g_Bh[rb + EDIM + e0]) = pack8(w2);
        }
        if (hasA) {
            float s = 0.f;
            #pragma unroll
            for (int i = 0; i < 8; i++) s += hv[i] * hv[i];
            s = wredsum(s);
            float inv = 1.f / fmaxf(sqrtf(s), 1e-12f);
            float v1[8], v2[8], cs = 0.f;
            #pragma unroll
            for (int i = 0; i < 8; i++) {
                float hh = hv[i] * inv * rh[i];
                v1[i] = rt[i] * rt[i];
                v2[i] = -2.f * rt[i] * hh;
                cs += hh * hh;
            }
            size_t ra = (size_t)b * KDIM;
            *reinterpret_cast<uint4*>(&g_Ah[ra + e0])        = pack8(v1);
            *reinterpret_cast<uint4*>(&g_Ah[ra + EDIM + e0]) = pack8(v2);
            cs = wredsum(cs);
            if (lane == 0) g_c[b] = cs;
        }
    }
    __threadfence();

    // ======== Phase 2: grid barrier (monotonic generation; replay-safe) ========
    __syncthreads();
    if (tid == 0) {
        unsigned long long ticket = atomicAdd(&g_bar, 1ULL);
        unsigned long long target = ((ticket >> 8) + 1) << 8;
        unsigned long long cur;
        do {
            asm volatile("ld.acquire.gpu.global.u64 %0, [%1];"
                         : "=l"(cur) : "l"(&g_bar));
            if (cur >= target) break;
            __nanosleep(64);
        } while (true);
    }
    __syncthreads();

    // ======== Phase 3: GEMM ========
    int wm = wid & 1;
    int wn = wid >> 1;
    int bn0 = blockIdx.x * BN;
    int bm0 = blockIdx.y * BM;
    int groupID = lane >> 2;
    int tig = lane & 3;

    // prefetch per-row constants
    int er0 = bm0 + wm * 32 + groupID;
    float cpre[2][2];
    cpre[0][0] = g_c[er0];
    cpre[0][1] = g_c[er0 + 8];
    cpre[1][0] = g_c[er0 + 16];
    cpre[1][1] = g_c[er0 + 24];

    float acc[2][4][4];
    #pragma unroll
    for (int mi = 0; mi < 2; mi++)
        #pragma unroll
        for (int ni = 0; ni < 4; ni++)
            #pragma unroll
            for (int q = 0; q < 4; q++) acc[mi][ni][q] = 0.f;

    uint32_t sbase = s2u(smem);

    int aRow = (lane & 7) + ((lane >> 3) & 1) * 8;
    int aKh  = (lane >> 4) * 8;
    int bRowOff = ((lane >> 4) & 1) * 8 + (lane & 7);
    int bKh     = ((lane >> 3) & 1) * 8;

    auto issue = [&](int ic) {
        if (ic < NCH) {
            uint32_t sD = sbase + (ic % STG) * STAGE_BYTES;
            int k0 = ic * KC;
            #pragma unroll
            for (int h = 0; h < 2; h++) {
                uint32_t aD = sD + h * 8192;
                uint32_t bD = sD + 16384 + h * 8192;
                int kh = k0 + h * 64;
                #pragma unroll
                for (int i = 0; i < 4; i++) {
                    int idx = i * 128 + tid;
                    int r = idx >> 3, c = idx & 7;
                    cpasync16(aD + sw128(r * 128 + c * 16),
                              &g_Ah[(size_t)(bm0 + r) * KDIM + kh + c * 8]);
                    cpasync16(bD + sw128(r * 128 + c * 16),
                              &g_Bh[(size_t)(bn0 + r) * KDIM + kh + c * 8]);
                }
            }
        }
        asm volatile("cp.async.commit_group;" ::: "memory");
    };

    // fragment loader for k-step kk (0..7) of the stage at sB
    auto load_frags = [&](uint32_t sB, int kk, uint32_t af[2][4], uint32_t bf[4][2]) {
        uint32_t aBase = sB + (kk >> 2) * 8192;
        uint32_t bBase = sB + 16384 + (kk >> 2) * 8192;
        int kq = kk & 3;
        #pragma unroll
        for (int mi = 0; mi < 2; mi++) {
            int row = wm * 32 + mi * 16 + aRow;
            int kcol = kq * 16 + aKh;
            uint32_t addr = aBase + sw128((uint32_t)(row * 128 + kcol * 2));
            asm volatile(
                "ldmatrix.sync.aligned.m8n8.x4.shared.b16 {%0,%1,%2,%3}, [%4];"
                : "=r"(af[mi][0]), "=r"(af[mi][1]), "=r"(af[mi][2]), "=r"(af[mi][3])
                : "r"(addr));
        }
        #pragma unroll
        for (int p = 0; p < 2; p++) {
            int n = wn * 32 + p * 16 + bRowOff;
            int kcol = kq * 16 + bKh;
            uint32_t addr = bBase + sw128((uint32_t)(n * 128 + kcol * 2));
            asm volatile(
                "ldmatrix.sync.aligned.m8n8.x4.shared.b16 {%0,%1,%2,%3}, [%4];"
                : "=r"(bf[p * 2][0]), "=r"(bf[p * 2][1]),
                  "=r"(bf[p * 2 + 1][0]), "=r"(bf[p * 2 + 1][1])
                : "r"(addr));
        }
    };

    auto do_mmas = [&](uint32_t af[2][4], uint32_t bf[4][2]) {
        #pragma unroll
        for (int mi = 0; mi < 2; mi++)
            #pragma unroll
            for (int ni = 0; ni < 4; ni++) {
                asm volatile(
                    "mma.sync.aligned.m16n8k16.row.col.f32.f16.f16.f32 "
                    "{%0,%1,%2,%3}, {%4,%5,%6,%7}, {%8,%9}, {%0,%1,%2,%3};"
                    : "+f"(acc[mi][ni][0]), "+f"(acc[mi][ni][1]),
                      "+f"(acc[mi][ni][2]), "+f"(acc[mi][ni][3])
                    : "r"(af[mi][0]), "r"(af[mi][1]), "r"(af[mi][2]), "r"(af[mi][3]),
                      "r"(bf[ni][0]), "r"(bf[ni][1]));
            }
    };

    issue(0);
    issue(1);

    uint32_t afb[2][2][4], bfb[2][4][2];    // double-buffered fragments

    #pragma unroll
    for (int it = 0; it < NCH; it++) {
        asm volatile("cp.async.wait_group 1;" ::: "memory");
        __syncthreads();
        issue(it + 2);

        uint32_t sB = sbase + (it % STG) * STAGE_BYTES;

        load_frags(sB, 0, afb[0], bfb[0]);
        #pragma unroll
        for (int kk = 0; kk < 8; kk++) {
            int cur = kk & 1;
            if (kk < 7) load_frags(sB, kk + 1, afb[cur ^ 1], bfb[cur ^ 1]);
            do_mmas(afb[cur], bfb[cur]);
        }
    }

    #pragma unroll
    for (int mi = 0; mi < 2; mi++) {
        int r0 = bm0 + wm * 32 + mi * 16 + groupID;
        int r1 = r0 + 8;
        float c0 = cpre[mi][0];
        float c1 = cpre[mi][1];
        #pragma unroll
        for (int ni = 0; ni < 4; ni++) {
            int col = bn0 + wn * 32 + ni * 8 + tig * 2;
            float2 v0, v1;
            v0.x = -sqrtf(fmaxf(acc[mi][ni][0] + c0, 0.f));
            v0.y = -sqrtf(fmaxf(acc[mi][ni][1] + c0, 0.f));
            v1.x = -sqrtf(fmaxf(acc[mi][ni][2] + c1, 0.f));
            v1.y = -sqrtf(fmaxf(acc[mi][ni][3] + c1, 0.f));
            *reinterpret_cast<float2*>(out + (size_t)r0 * NNEG + col) = v0;
            *reinterpret_cast<float2*>(out + (size_t)r1 * NNEG + col) = v1;
        }
    }
}

// ---------------------------------------------------------------------------
extern "C" void kernel_launch(void* const* d_in, const int* in_sizes, int n_in,
                              void* d_out, int out_size) {
    const float* head = (const float*)d_in[0];       // (512, 256)
    const float* tail = (const float*)d_in[1];       // (1, 2048, 256)
    const float* rel  = (const float*)d_in[2];       // (1000, 512)
    const int*   rid  = (const int*)d_in[3];         // (512,) int32
    float* out = (float*)d_out;                      // (512, 2048)

    cudaFuncSetAttribute(fused_kernel,
                         cudaFuncAttributeMaxDynamicSharedMemorySize, SM_TOTAL);
    dim3 grid(NNEG / BN, BATCH / BM);                // 32 x 8 = 256 CTAs
    fused_kernel<<<grid, 128, SM_TOTAL>>>(out, head, tail, rel, rid);
}